// round 12
// baseline (speedup 1.0000x reference)
#include <cuda_runtime.h>
#include <math.h>

// Problem dims
#define BB   8
#define SSQ  1024
#define EE   128
#define HHN  8
#define DDQ  128
#define HDD  1024
#define MTOT (BB*SSQ)   // 8192

#define LDT  132        // smem row stride (floats) for 128-wide tiles

// Scratch (device globals; no allocation allowed)
static __device__ float g_Q[BB*HHN*SSQ*DDQ];  // [B,H,S,D]
static __device__ float g_K[BB*HHN*SSQ*DDQ];
static __device__ float g_V[BB*HHN*SSQ*DDQ];
static __device__ float g_O[MTOT*HDD];        // [B,S,HD]

// Load a 64x128 fp32 tile (row stride ldg in gmem) into smem with row stride LDT.
// 256 threads, float4 coalesced loads, conflict-free float4 stores.
__device__ __forceinline__ void load_tile_64x128(const float* __restrict__ g, int ldg,
                                                 float* __restrict__ s, int t) {
    const int c4 = t & 31;        // float4 column
    const int r0 = t >> 5;        // 8 rows per pass
#pragma unroll
    for (int p = 0; p < 8; ++p) {
        const int r = r0 + p * 8;
        float4 v = *(const float4*)(g + (size_t)r * ldg + c4 * 4);
        *(float4*)(s + r * LDT + c4 * 4) = v;
    }
}

// ---------------------------------------------------------------------------
// Kernel 1: QKV projection.  Out[b,h,s,d] = sum_e X[b,s,e] * W[h*128+d, e]
// grid = (16 nTiles, 128 mTiles, 3 matrices), block = 256
// ---------------------------------------------------------------------------
__global__ __launch_bounds__(256) void proj_kernel(
    const float* __restrict__ q, const float* __restrict__ k, const float* __restrict__ v,
    const float* __restrict__ Wq, const float* __restrict__ Wk, const float* __restrict__ Wv)
{
    extern __shared__ float sm[];
    float* As = sm;              // 64*LDT
    float* Bs = sm + 64 * LDT;   // 64*LDT

    const int t = threadIdx.x;
    const float* X; const float* W; float* Out;
    if (blockIdx.z == 0)      { X = q; W = Wq; Out = g_Q; }
    else if (blockIdx.z == 1) { X = k; W = Wk; Out = g_K; }
    else                      { X = v; W = Wv; Out = g_V; }

    const int mBase = blockIdx.y * 64;
    const int nBase = blockIdx.x * 64;

    load_tile_64x128(X + (size_t)mBase * EE, EE, As, t);
    load_tile_64x128(W + (size_t)nBase * EE, EE, Bs, t);
    __syncthreads();

    const int tx = t & 15, ty = t >> 4;
    float acc[4][4];
#pragma unroll
    for (int i = 0; i < 4; i++)
#pragma unroll
        for (int j = 0; j < 4; j++) acc[i][j] = 0.f;

#pragma unroll 2
    for (int kk = 0; kk < 128; kk += 4) {
        float4 a[4], b[4];
#pragma unroll
        for (int i = 0; i < 4; i++) a[i] = *(const float4*)(As + (ty * 4 + i) * LDT + kk);
#pragma unroll
        for (int j = 0; j < 4; j++) b[j] = *(const float4*)(Bs + (tx + 16 * j) * LDT + kk);
#pragma unroll
        for (int i = 0; i < 4; i++)
#pragma unroll
            for (int j = 0; j < 4; j++)
                acc[i][j] += a[i].x * b[j].x + a[i].y * b[j].y +
                             a[i].z * b[j].z + a[i].w * b[j].w;
    }

#pragma unroll
    for (int i = 0; i < 4; i++) {
        const int row = mBase + ty * 4 + i;
        const int bb = row >> 10, s = row & 1023;
#pragma unroll
        for (int j = 0; j < 4; j++) {
            const int col = nBase + tx + 16 * j;
            const int h = col >> 7, d = col & 127;
            Out[(((size_t)bb * HHN + h) * SSQ + s) * DDQ + d] = acc[i][j];
        }
    }
}

// ---------------------------------------------------------------------------
// Kernel 2: flash attention per (b,h).  grid = (16 qTiles, 64 bh), block = 256
// ---------------------------------------------------------------------------
__global__ __launch_bounds__(256, 2) void attn_kernel(const float* __restrict__ mask)
{
    extern __shared__ float sm[];
    float* Qs   = sm;                         // 64*LDT
    float* KVs  = Qs + 64 * LDT;              // 64*LDT (K, then reused for V)
    float* Ss   = KVs + 64 * LDT;             // 64*68
    float* rowM = Ss + 64 * 68;               // 64
    float* rowL = rowM + 64;                  // 64
    float* rowA = rowL + 64;                  // 64

    const int t  = threadIdx.x;
    const int bh = blockIdx.y;                // 0..63
    const int b  = bh >> 3;
    const int qBase = blockIdx.x * 64;

    const float* Qg = g_Q + (size_t)bh * SSQ * DDQ + (size_t)qBase * DDQ;
    const float* Kg = g_K + (size_t)bh * SSQ * DDQ;
    const float* Vg = g_V + (size_t)bh * SSQ * DDQ;

    if (t < 64) { rowM[t] = -INFINITY; rowL[t] = 0.f; }
    load_tile_64x128(Qg, DDQ, Qs, t);
    __syncthreads();

    const int tx = t & 15, ty = t >> 4;
    const int r = t >> 2, qq = t & 3;         // softmax: 4 threads per row
    const float scale = 0.08838834764831845f; // 1/sqrt(128)
    const float* mrow = mask + (size_t)b * SSQ;

    float o[4][8];
#pragma unroll
    for (int i = 0; i < 4; i++)
#pragma unroll
        for (int j = 0; j < 8; j++) o[i][j] = 0.f;

    for (int kb = 0; kb < 16; ++kb) {
        // ---- load K block ----
        load_tile_64x128(Kg + (size_t)kb * 64 * DDQ, DDQ, KVs, t);
        __syncthreads();

        // ---- S = Q K^T (64x64) ----
        float s4[4][4];
#pragma unroll
        for (int i = 0; i < 4; i++)
#pragma unroll
            for (int j = 0; j < 4; j++) s4[i][j] = 0.f;

#pragma unroll 2
        for (int kk = 0; kk < 128; kk += 4) {
            float4 a[4], bb4[4];
#pragma unroll
            for (int i = 0; i < 4; i++) a[i]   = *(const float4*)(Qs  + (ty * 4 + i) * LDT + kk);
#pragma unroll
            for (int j = 0; j < 4; j++) bb4[j] = *(const float4*)(KVs + (tx + 16 * j) * LDT + kk);
#pragma unroll
            for (int i = 0; i < 4; i++)
#pragma unroll
                for (int j = 0; j < 4; j++)
                    s4[i][j] += a[i].x * bb4[j].x + a[i].y * bb4[j].y +
                                a[i].z * bb4[j].z + a[i].w * bb4[j].w;
        }
#pragma unroll
        for (int i = 0; i < 4; i++)
#pragma unroll
            for (int j = 0; j < 4; j++)
                Ss[(ty * 4 + i) * 68 + tx + 16 * j] = s4[i][j];
        __syncthreads();

        // ---- load V block into the same buffer (K is dead) ----
        load_tile_64x128(Vg + (size_t)kb * 64 * DDQ, DDQ, KVs, t);

        // ---- online softmax on Ss rows (4 threads per row, 16 cols each) ----
        {
            const float* mk = mrow + kb * 64 + qq * 16;
            float vbuf[16];
            float mx = -INFINITY;
#pragma unroll
            for (int c = 0; c < 16; c++) {
                float x = Ss[r * 68 + qq * 16 + c] * scale + mk[c];
                vbuf[c] = x;
                mx = fmaxf(mx, x);
            }
            mx = fmaxf(mx, __shfl_xor_sync(0xffffffffu, mx, 1));
            mx = fmaxf(mx, __shfl_xor_sync(0xffffffffu, mx, 2));
            const float mOld = rowM[r];
            const float mNew = fmaxf(mOld, mx);
            float sum = 0.f;
#pragma unroll
            for (int c = 0; c < 16; c++) {
                float p = __expf(vbuf[c] - mNew);
                Ss[r * 68 + qq * 16 + c] = p;
                sum += p;
            }
            sum += __shfl_xor_sync(0xffffffffu, sum, 1);
            sum += __shfl_xor_sync(0xffffffffu, sum, 2);
            if (qq == 0) {
                const float alpha = __expf(mOld - mNew);
                rowL[r] = rowL[r] * alpha + sum;
                rowM[r] = mNew;
                rowA[r] = alpha;
            }
        }
        __syncthreads();

        // ---- rescale O and accumulate P @ V ----
        float al[4];
#pragma unroll
        for (int i = 0; i < 4; i++) al[i] = rowA[ty * 4 + i];
#pragma unroll
        for (int i = 0; i < 4; i++)
#pragma unroll
            for (int j = 0; j < 8; j++) o[i][j] *= al[i];

#pragma unroll 2
        for (int n = 0; n < 64; ++n) {
            float p[4];
#pragma unroll
            for (int i = 0; i < 4; i++) p[i] = Ss[(ty * 4 + i) * 68 + n];
            const float4 v0 = *(const float4*)(KVs + n * LDT + tx * 4);
            const float4 v1 = *(const float4*)(KVs + n * LDT + tx * 4 + 64);
#pragma unroll
            for (int i = 0; i < 4; i++) {
                o[i][0] += p[i] * v0.x;  o[i][1] += p[i] * v0.y;
                o[i][2] += p[i] * v0.z;  o[i][3] += p[i] * v0.w;
                o[i][4] += p[i] * v1.x;  o[i][5] += p[i] * v1.y;
                o[i][6] += p[i] * v1.z;  o[i][7] += p[i] * v1.w;
            }
        }
        __syncthreads();
    }

    // ---- finalize: divide by row sums, write [B,S,HD] ----
    const int h = bh & 7;
#pragma unroll
    for (int i = 0; i < 4; i++) {
        const float inv = 1.f / (rowL[ty * 4 + i] + 1e-12f);
        const int srow = qBase + ty * 4 + i;
        float* oPtr = g_O + ((size_t)b * SSQ + srow) * HDD + h * DDQ;
        float4 w0 = make_float4(o[i][0] * inv, o[i][1] * inv, o[i][2] * inv, o[i][3] * inv);
        float4 w1 = make_float4(o[i][4] * inv, o[i][5] * inv, o[i][6] * inv, o[i][7] * inv);
        *(float4*)(oPtr + tx * 4)      = w0;
        *(float4*)(oPtr + tx * 4 + 64) = w1;
    }
}

// ---------------------------------------------------------------------------
// Kernel 3: output projection.  out = g_O[8192,1024] @ Wc^T[1024,128] + bc
// grid = (2 nTiles, 128 mTiles), block = 256
// ---------------------------------------------------------------------------
__global__ __launch_bounds__(256) void oproj_kernel(
    const float* __restrict__ Wc, const float* __restrict__ bc, float* __restrict__ out)
{
    extern __shared__ float sm[];
    float* As = sm;
    float* Bs = sm + 64 * LDT;

    const int t = threadIdx.x;
    const int mBase = blockIdx.y * 64;
    const int nBase = blockIdx.x * 64;
    const int tx = t & 15, ty = t >> 4;

    float acc[4][4];
#pragma unroll
    for (int i = 0; i < 4; i++)
#pragma unroll
        for (int j = 0; j < 4; j++) acc[i][j] = 0.f;

    for (int kc = 0; kc < HDD; kc += 128) {
        __syncthreads();
        load_tile_64x128(g_O + (size_t)mBase * HDD + kc, HDD, As, t);
        load_tile_64x128(Wc  + (size_t)nBase * HDD + kc, HDD, Bs, t);
        __syncthreads();

#pragma unroll 2
        for (int kk = 0; kk < 128; kk += 4) {
            float4 a[4], b[4];
#pragma unroll
            for (int i = 0; i < 4; i++) a[i] = *(const float4*)(As + (ty * 4 + i) * LDT + kk);
#pragma unroll
            for (int j = 0; j < 4; j++) b[j] = *(const float4*)(Bs + (tx + 16 * j) * LDT + kk);
#pragma unroll
            for (int i = 0; i < 4; i++)
#pragma unroll
                for (int j = 0; j < 4; j++)
                    acc[i][j] += a[i].x * b[j].x + a[i].y * b[j].y +
                                 a[i].z * b[j].z + a[i].w * b[j].w;
        }
    }

#pragma unroll
    for (int i = 0; i < 4; i++) {
        const int row = mBase + ty * 4 + i;
#pragma unroll
        for (int j = 0; j < 4; j++) {
            const int col = nBase + tx + 16 * j;
            out[(size_t)row * EE + col] = acc[i][j] + bc[col];
        }
    }
}

// ---------------------------------------------------------------------------
extern "C" void kernel_launch(void* const* d_in, const int* in_sizes, int n_in,
                              void* d_out, int out_size)
{
    (void)in_sizes; (void)n_in; (void)out_size;
    const float* q    = (const float*)d_in[0];
    const float* k    = (const float*)d_in[1];
    const float* v    = (const float*)d_in[2];
    const float* mask = (const float*)d_in[3];
    const float* Wq   = (const float*)d_in[4];
    const float* Wk   = (const float*)d_in[5];
    const float* Wv   = (const float*)d_in[6];
    const float* Wc   = (const float*)d_in[7];
    const float* bc   = (const float*)d_in[8];
    float* out = (float*)d_out;

    const int gemmSmem = 2 * 64 * LDT * 4;                      // 67584 B
    const int attnSmem = (2 * 64 * LDT + 64 * 68 + 3 * 64) * 4; // 85760 B

    cudaFuncSetAttribute(proj_kernel,  cudaFuncAttributeMaxDynamicSharedMemorySize, gemmSmem);
    cudaFuncSetAttribute(attn_kernel,  cudaFuncAttributeMaxDynamicSharedMemorySize, attnSmem);
    cudaFuncSetAttribute(oproj_kernel, cudaFuncAttributeMaxDynamicSharedMemorySize, gemmSmem);

    proj_kernel <<<dim3(16, 128, 3), 256, gemmSmem>>>(q, k, v, Wq, Wk, Wv);
    attn_kernel <<<dim3(16, 64),     256, attnSmem>>>(mask);
    oproj_kernel<<<dim3(2, 128),     256, gemmSmem>>>(Wc, bc, out);
}

// round 13
// speedup vs baseline: 1.9235x; 1.9235x over previous
#include <cuda_runtime.h>
#include <math.h>

// Problem dims
#define BB   8
#define SSQ  1024
#define EE   128
#define HHN  8
#define DDQ  128
#define HDD  1024
#define MTOT (BB*SSQ)   // 8192

#define LDT  132        // smem row stride (floats) for 128-wide fp32 tiles (proj/oproj)
#define LDK  132        // attn: Q/K tile stride  (bank: 132%32=4 -> conflict-free frag loads)
#define LDV  136        // attn: V tile stride    (bank: 136%32=8 -> conflict-free B-frag loads)
#define LDS_ 68         // attn: S/P tile stride

// Scratch (device globals; no allocation allowed)
static __device__ float g_Q[BB*HHN*SSQ*DDQ];  // [B,H,S,D]
static __device__ float g_K[BB*HHN*SSQ*DDQ];
static __device__ float g_V[BB*HHN*SSQ*DDQ];
static __device__ float g_O[MTOT*HDD];        // [B,S,HD]

// ---------------------------------------------------------------------------
// helpers
// ---------------------------------------------------------------------------
__device__ __forceinline__ unsigned f2tf(float x) {
    unsigned r;
    asm("cvt.rna.tf32.f32 %0, %1;" : "=r"(r) : "f"(x));
    return r;
}

// D += A(16x8,row) * B(8x8,col)  tf32, fp32 accum
__device__ __forceinline__ void mma_tf32(float* d,
    unsigned a0, unsigned a1, unsigned a2, unsigned a3,
    unsigned b0, unsigned b1)
{
    asm volatile(
        "mma.sync.aligned.m16n8k8.row.col.f32.tf32.tf32.f32 "
        "{%0,%1,%2,%3}, {%4,%5,%6,%7}, {%8,%9}, {%0,%1,%2,%3};"
        : "+f"(d[0]), "+f"(d[1]), "+f"(d[2]), "+f"(d[3])
        : "r"(a0), "r"(a1), "r"(a2), "r"(a3), "r"(b0), "r"(b1));
}

// 64x128 fp32 tile gmem->smem, coalesced float4, conflict-free stores.
__device__ __forceinline__ void load_tile_64x128(const float* __restrict__ g, int ldg,
                                                 float* __restrict__ s, int t) {
    const int c4 = t & 31;
    const int r0 = t >> 5;
#pragma unroll
    for (int p = 0; p < 8; ++p) {
        const int r = r0 + p * 8;
        float4 v = *(const float4*)(g + (size_t)r * ldg + c4 * 4);
        *(float4*)(s + r * LDT + c4 * 4) = v;
    }
}

// same, but convert to tf32 at store; runtime smem stride
__device__ __forceinline__ void load_tile_tf32(const float* __restrict__ g, int ldg,
                                               float* __restrict__ s, int ldt, int t) {
    const int c4 = t & 31;
    const int r0 = t >> 5;
#pragma unroll
    for (int p = 0; p < 8; ++p) {
        const int r = r0 + p * 8;
        float4 v = *(const float4*)(g + (size_t)r * ldg + c4 * 4);
        v.x = __uint_as_float(f2tf(v.x));
        v.y = __uint_as_float(f2tf(v.y));
        v.z = __uint_as_float(f2tf(v.z));
        v.w = __uint_as_float(f2tf(v.w));
        *(float4*)(s + r * ldt + c4 * 4) = v;
    }
}

// ---------------------------------------------------------------------------
// Kernel 1: QKV projection (unchanged).  grid=(16,128,3), block=256
// ---------------------------------------------------------------------------
__global__ __launch_bounds__(256) void proj_kernel(
    const float* __restrict__ q, const float* __restrict__ k, const float* __restrict__ v,
    const float* __restrict__ Wq, const float* __restrict__ Wk, const float* __restrict__ Wv)
{
    extern __shared__ float sm[];
    float* As = sm;
    float* Bs = sm + 64 * LDT;

    const int t = threadIdx.x;
    const float* X; const float* W; float* Out;
    if (blockIdx.z == 0)      { X = q; W = Wq; Out = g_Q; }
    else if (blockIdx.z == 1) { X = k; W = Wk; Out = g_K; }
    else                      { X = v; W = Wv; Out = g_V; }

    const int mBase = blockIdx.y * 64;
    const int nBase = blockIdx.x * 64;

    load_tile_64x128(X + (size_t)mBase * EE, EE, As, t);
    load_tile_64x128(W + (size_t)nBase * EE, EE, Bs, t);
    __syncthreads();

    const int tx = t & 15, ty = t >> 4;
    float acc[4][4];
#pragma unroll
    for (int i = 0; i < 4; i++)
#pragma unroll
        for (int j = 0; j < 4; j++) acc[i][j] = 0.f;

#pragma unroll 2
    for (int kk = 0; kk < 128; kk += 4) {
        float4 a[4], b[4];
#pragma unroll
        for (int i = 0; i < 4; i++) a[i] = *(const float4*)(As + (ty * 4 + i) * LDT + kk);
#pragma unroll
        for (int j = 0; j < 4; j++) b[j] = *(const float4*)(Bs + (tx + 16 * j) * LDT + kk);
#pragma unroll
        for (int i = 0; i < 4; i++)
#pragma unroll
            for (int j = 0; j < 4; j++)
                acc[i][j] += a[i].x * b[j].x + a[i].y * b[j].y +
                             a[i].z * b[j].z + a[i].w * b[j].w;
    }

#pragma unroll
    for (int i = 0; i < 4; i++) {
        const int row = mBase + ty * 4 + i;
        const int bb = row >> 10, s = row & 1023;
#pragma unroll
        for (int j = 0; j < 4; j++) {
            const int col = nBase + tx + 16 * j;
            const int h = col >> 7, d = col & 127;
            Out[(((size_t)bb * HHN + h) * SSQ + s) * DDQ + d] = acc[i][j];
        }
    }
}

// ---------------------------------------------------------------------------
// Kernel 2: flash attention, tensor-core (mma.sync tf32) QK^T and PV.
// grid = (16 qTiles, 64 bh), block = 256 (8 warps)
// Warp w: m-block mb=w&3 (16 rows), n-half nh=w>>2.
//   QK: warp computes S rows [16mb,16mb+16) x cols [32nh,32nh+32)  (4 n-tiles)
//   PV: warp computes O rows [16mb,16mb+16) x cols [64nh,64nh+64)  (8 n-tiles)
// ---------------------------------------------------------------------------
__global__ __launch_bounds__(256, 2) void attn_kernel(const float* __restrict__ mask)
{
    extern __shared__ float sm[];
    float* Qs   = sm;                          // 64*LDK   (tf32)
    float* KVs  = Qs + 64 * LDK;               // 64*LDV   (K tf32 @LDK, then V tf32 @LDV)
    float* Ss   = KVs + 64 * LDV;              // 64*LDS_  (S raw fp32, then P tf32)
    float* rowM = Ss + 64 * LDS_;              // 64
    float* rowL = rowM + 64;                   // 64
    float* rowA = rowL + 64;                   // 64

    const int t    = threadIdx.x;
    const int lane = t & 31;
    const int warp = t >> 5;
    const int g    = lane >> 2;                // 0..7
    const int tig  = lane & 3;                 // 0..3
    const int mb   = warp & 3;                 // m block
    const int nh   = warp >> 2;                // n half

    const int bh = blockIdx.y;
    const int b  = bh >> 3;
    const int qBase = blockIdx.x * 64;

    const float* Qg = g_Q + (size_t)bh * SSQ * DDQ + (size_t)qBase * DDQ;
    const float* Kg = g_K + (size_t)bh * SSQ * DDQ;
    const float* Vg = g_V + (size_t)bh * SSQ * DDQ;

    if (t < 64) { rowM[t] = -INFINITY; rowL[t] = 0.f; }
    load_tile_tf32(Qg, DDQ, Qs, LDK, t);
    __syncthreads();

    const int r = t >> 2, qq = t & 3;          // softmax mapping (unchanged)
    const float scale = 0.08838834764831845f;  // 1/sqrt(128)
    const float* mrow = mask + (size_t)b * SSQ;

    // O accumulator fragments: 8 n-tiles x {c0,c1,c2,c3}
    float o[8][4];
#pragma unroll
    for (int i = 0; i < 8; i++)
#pragma unroll
        for (int j = 0; j < 4; j++) o[i][j] = 0.f;

    const int rowLo = mb * 16 + g;             // fragment row (c0,c1)
    const int rowHi = rowLo + 8;               // fragment row (c2,c3)

    for (int kb = 0; kb < 16; ++kb) {
        // ---- load K block (tf32, stride LDK) ----
        load_tile_tf32(Kg + (size_t)kb * 64 * DDQ, DDQ, KVs, LDK, t);
        __syncthreads();

        // ---- S = Q K^T via mma ----
        float sAcc[4][4];
#pragma unroll
        for (int i = 0; i < 4; i++)
#pragma unroll
            for (int j = 0; j < 4; j++) sAcc[i][j] = 0.f;

#pragma unroll 4
        for (int k8 = 0; k8 < 16; ++k8) {
            const int kk = k8 * 8;
            const float* qb = Qs + rowLo * LDK + kk;
            unsigned a0 = __float_as_uint(qb[tig]);
            unsigned a1 = __float_as_uint(qb[8 * LDK + tig]);
            unsigned a2 = __float_as_uint(qb[tig + 4]);
            unsigned a3 = __float_as_uint(qb[8 * LDK + tig + 4]);
#pragma unroll
            for (int nt = 0; nt < 4; ++nt) {
                const int n = nh * 32 + nt * 8 + g;
                unsigned b0 = __float_as_uint(KVs[n * LDK + kk + tig]);
                unsigned b1 = __float_as_uint(KVs[n * LDK + kk + tig + 4]);
                mma_tf32(sAcc[nt], a0, a1, a2, a3, b0, b1);
            }
        }
        // store raw S fragments (scale+mask applied in softmax, as before)
#pragma unroll
        for (int nt = 0; nt < 4; ++nt) {
            const int col = nh * 32 + nt * 8 + 2 * tig;
            *(float2*)(Ss + rowLo * LDS_ + col) = make_float2(sAcc[nt][0], sAcc[nt][1]);
            *(float2*)(Ss + rowHi * LDS_ + col) = make_float2(sAcc[nt][2], sAcc[nt][3]);
        }
        __syncthreads();

        // ---- load V block (tf32, stride LDV) into same buffer (K dead) ----
        load_tile_tf32(Vg + (size_t)kb * 64 * DDQ, DDQ, KVs, LDV, t);

        // ---- online softmax (unchanged math; P stored tf32-rounded) ----
        {
            const float* mk = mrow + kb * 64 + qq * 16;
            float vbuf[16];
            float mx = -INFINITY;
#pragma unroll
            for (int c = 0; c < 16; c++) {
                float x = Ss[r * LDS_ + qq * 16 + c] * scale + mk[c];
                vbuf[c] = x;
                mx = fmaxf(mx, x);
            }
            mx = fmaxf(mx, __shfl_xor_sync(0xffffffffu, mx, 1));
            mx = fmaxf(mx, __shfl_xor_sync(0xffffffffu, mx, 2));
            const float mOld = rowM[r];
            const float mNew = fmaxf(mOld, mx);
            float sum = 0.f;
#pragma unroll
            for (int c = 0; c < 16; c++) {
                float p = __expf(vbuf[c] - mNew);
                Ss[r * LDS_ + qq * 16 + c] = __uint_as_float(f2tf(p));
                sum += p;
            }
            sum += __shfl_xor_sync(0xffffffffu, sum, 1);
            sum += __shfl_xor_sync(0xffffffffu, sum, 2);
            if (qq == 0) {
                const float alpha = __expf(mOld - mNew);
                rowL[r] = rowL[r] * alpha + sum;
                rowM[r] = mNew;
                rowA[r] = alpha;
            }
        }
        __syncthreads();

        // ---- rescale O fragments, accumulate P @ V via mma ----
        {
            const float al0 = rowA[rowLo];
            const float al1 = rowA[rowHi];
#pragma unroll
            for (int nt = 0; nt < 8; ++nt) {
                o[nt][0] *= al0;  o[nt][1] *= al0;
                o[nt][2] *= al1;  o[nt][3] *= al1;
            }
#pragma unroll 2
            for (int k8 = 0; k8 < 8; ++k8) {
                const int kk = k8 * 8;
                const float* pb = Ss + rowLo * LDS_ + kk;
                unsigned a0 = __float_as_uint(pb[tig]);
                unsigned a1 = __float_as_uint(pb[8 * LDS_ + tig]);
                unsigned a2 = __float_as_uint(pb[tig + 4]);
                unsigned a3 = __float_as_uint(pb[8 * LDS_ + tig + 4]);
#pragma unroll
                for (int nt = 0; nt < 8; ++nt) {
                    const int n = nh * 64 + nt * 8 + g;
                    unsigned b0 = __float_as_uint(KVs[(kk + tig) * LDV + n]);
                    unsigned b1 = __float_as_uint(KVs[(kk + tig + 4) * LDV + n]);
                    mma_tf32(o[nt], a0, a1, a2, a3, b0, b1);
                }
            }
        }
        __syncthreads();
    }

    // ---- finalize: divide by row sums, write [B,S,HD] ----
    const int h = bh & 7;
    const float inv0 = 1.f / (rowL[rowLo] + 1e-12f);
    const float inv1 = 1.f / (rowL[rowHi] + 1e-12f);
    float* oLo = g_O + ((size_t)b * SSQ + qBase + rowLo) * HDD + h * DDQ;
    float* oHi = g_O + ((size_t)b * SSQ + qBase + rowHi) * HDD + h * DDQ;
#pragma unroll
    for (int nt = 0; nt < 8; ++nt) {
        const int col = nh * 64 + nt * 8 + 2 * tig;
        *(float2*)(oLo + col) = make_float2(o[nt][0] * inv0, o[nt][1] * inv0);
        *(float2*)(oHi + col) = make_float2(o[nt][2] * inv1, o[nt][3] * inv1);
    }
}

// ---------------------------------------------------------------------------
// Kernel 3: output projection (unchanged).  grid=(2,128), block=256
// ---------------------------------------------------------------------------
__global__ __launch_bounds__(256) void oproj_kernel(
    const float* __restrict__ Wc, const float* __restrict__ bc, float* __restrict__ out)
{
    extern __shared__ float sm[];
    float* As = sm;
    float* Bs = sm + 64 * LDT;

    const int t = threadIdx.x;
    const int mBase = blockIdx.y * 64;
    const int nBase = blockIdx.x * 64;
    const int tx = t & 15, ty = t >> 4;

    float acc[4][4];
#pragma unroll
    for (int i = 0; i < 4; i++)
#pragma unroll
        for (int j = 0; j < 4; j++) acc[i][j] = 0.f;

    for (int kc = 0; kc < HDD; kc += 128) {
        __syncthreads();
        load_tile_64x128(g_O + (size_t)mBase * HDD + kc, HDD, As, t);
        load_tile_64x128(Wc  + (size_t)nBase * HDD + kc, HDD, Bs, t);
        __syncthreads();

#pragma unroll 2
        for (int kk = 0; kk < 128; kk += 4) {
            float4 a[4], b[4];
#pragma unroll
            for (int i = 0; i < 4; i++) a[i] = *(const float4*)(As + (ty * 4 + i) * LDT + kk);
#pragma unroll
            for (int j = 0; j < 4; j++) b[j] = *(const float4*)(Bs + (tx + 16 * j) * LDT + kk);
#pragma unroll
            for (int i = 0; i < 4; i++)
#pragma unroll
                for (int j = 0; j < 4; j++)
                    acc[i][j] += a[i].x * b[j].x + a[i].y * b[j].y +
                                 a[i].z * b[j].z + a[i].w * b[j].w;
        }
    }

#pragma unroll
    for (int i = 0; i < 4; i++) {
        const int row = mBase + ty * 4 + i;
#pragma unroll
        for (int j = 0; j < 4; j++) {
            const int col = nBase + tx + 16 * j;
            out[(size_t)row * EE + col] = acc[i][j] + bc[col];
        }
    }
}

// ---------------------------------------------------------------------------
extern "C" void kernel_launch(void* const* d_in, const int* in_sizes, int n_in,
                              void* d_out, int out_size)
{
    (void)in_sizes; (void)n_in; (void)out_size;
    const float* q    = (const float*)d_in[0];
    const float* k    = (const float*)d_in[1];
    const float* v    = (const float*)d_in[2];
    const float* mask = (const float*)d_in[3];
    const float* Wq   = (const float*)d_in[4];
    const float* Wk   = (const float*)d_in[5];
    const float* Wv   = (const float*)d_in[6];
    const float* Wc   = (const float*)d_in[7];
    const float* bc   = (const float*)d_in[8];
    float* out = (float*)d_out;

    const int gemmSmem = 2 * 64 * LDT * 4;                                  // 67584 B
    const int attnSmem = (64 * LDK + 64 * LDV + 64 * LDS_ + 3 * 64) * 4;    // 86784 B

    cudaFuncSetAttribute(proj_kernel,  cudaFuncAttributeMaxDynamicSharedMemorySize, gemmSmem);
    cudaFuncSetAttribute(attn_kernel,  cudaFuncAttributeMaxDynamicSharedMemorySize, attnSmem);
    cudaFuncSetAttribute(oproj_kernel, cudaFuncAttributeMaxDynamicSharedMemorySize, gemmSmem);

    proj_kernel <<<dim3(16, 128, 3), 256, gemmSmem>>>(q, k, v, Wq, Wk, Wv);
    attn_kernel <<<dim3(16, 64),     256, attnSmem>>>(mask);
    oproj_kernel<<<dim3(2, 128),     256, gemmSmem>>>(Wc, bc, out);
}

// round 14
// speedup vs baseline: 2.5034x; 1.3015x over previous
#include <cuda_runtime.h>
#include <math.h>

// Problem dims
#define BB   8
#define SSQ  1024
#define EE   128
#define HHN  8
#define DDQ  128
#define HDD  1024
#define MTOT (BB*SSQ)   // 8192

#define LDK  132        // smem stride: A/B tf32 tiles (132%32=4 -> conflict-free frag loads)
#define LDV  136        // attn: V tile stride (136%32=8 -> conflict-free B-frag loads)
#define LDS_ 68         // attn: S/P tile stride

// Scratch (device globals; no allocation allowed)
static __device__ float g_Q[BB*HHN*SSQ*DDQ];  // [B,H,S,D]
static __device__ float g_K[BB*HHN*SSQ*DDQ];
static __device__ float g_V[BB*HHN*SSQ*DDQ];
static __device__ float g_O[MTOT*HDD];        // [B,S,HD]

// ---------------------------------------------------------------------------
// helpers
// ---------------------------------------------------------------------------
__device__ __forceinline__ unsigned f2tf(float x) {
    unsigned r;
    asm("cvt.rna.tf32.f32 %0, %1;" : "=r"(r) : "f"(x));
    return r;
}

// D += A(16x8,row) * B(8x8,col)  tf32, fp32 accum  (fragment map HW-verified R13)
__device__ __forceinline__ void mma_tf32(float* d,
    unsigned a0, unsigned a1, unsigned a2, unsigned a3,
    unsigned b0, unsigned b1)
{
    asm volatile(
        "mma.sync.aligned.m16n8k8.row.col.f32.tf32.tf32.f32 "
        "{%0,%1,%2,%3}, {%4,%5,%6,%7}, {%8,%9}, {%0,%1,%2,%3};"
        : "+f"(d[0]), "+f"(d[1]), "+f"(d[2]), "+f"(d[3])
        : "r"(a0), "r"(a1), "r"(a2), "r"(a3), "r"(b0), "r"(b1));
}

// 64x128 fp32 tile gmem->smem with tf32 convert; runtime smem stride.
__device__ __forceinline__ void load_tile_tf32(const float* __restrict__ g, int ldg,
                                               float* __restrict__ s, int ldt, int t) {
    const int c4 = t & 31;
    const int r0 = t >> 5;
#pragma unroll
    for (int p = 0; p < 8; ++p) {
        const int r = r0 + p * 8;
        float4 v = *(const float4*)(g + (size_t)r * ldg + c4 * 4);
        v.x = __uint_as_float(f2tf(v.x));
        v.y = __uint_as_float(f2tf(v.y));
        v.z = __uint_as_float(f2tf(v.z));
        v.w = __uint_as_float(f2tf(v.w));
        *(float4*)(s + r * ldt + c4 * 4) = v;
    }
}

// Core 64x64x128 warp-mma: As(64x128 row-major), Bs(64x128 n-major), acc[4][4].
__device__ __forceinline__ void mma_tile_64x64(const float* As, const float* Bs,
                                               float acc[4][4], int mb, int nh,
                                               int g, int tig)
{
#pragma unroll 4
    for (int k8 = 0; k8 < 16; ++k8) {
        const int kk = k8 * 8;
        const float* ab = As + (mb * 16 + g) * LDK + kk;
        unsigned a0 = __float_as_uint(ab[tig]);
        unsigned a1 = __float_as_uint(ab[8 * LDK + tig]);
        unsigned a2 = __float_as_uint(ab[tig + 4]);
        unsigned a3 = __float_as_uint(ab[tig + 4 + 8 * LDK]);
#pragma unroll
        for (int nt = 0; nt < 4; ++nt) {
            const int n = nh * 32 + nt * 8 + g;
            unsigned b0 = __float_as_uint(Bs[n * LDK + kk + tig]);
            unsigned b1 = __float_as_uint(Bs[n * LDK + kk + tig + 4]);
            mma_tf32(acc[nt], a0, a1, a2, a3, b0, b1);
        }
    }
}

// ---------------------------------------------------------------------------
// Kernel 1: QKV projection via tf32 mma.  grid=(16,128,3), block=256
// ---------------------------------------------------------------------------
__global__ __launch_bounds__(256, 2) void proj_kernel(
    const float* __restrict__ q, const float* __restrict__ k, const float* __restrict__ v,
    const float* __restrict__ Wq, const float* __restrict__ Wk, const float* __restrict__ Wv)
{
    extern __shared__ float sm[];
    float* As = sm;              // X tile 64x128 tf32
    float* Bs = sm + 64 * LDK;   // W tile 64x128 tf32

    const int t = threadIdx.x;
    const float* X; const float* W; float* Out;
    if (blockIdx.z == 0)      { X = q; W = Wq; Out = g_Q; }
    else if (blockIdx.z == 1) { X = k; W = Wk; Out = g_K; }
    else                      { X = v; W = Wv; Out = g_V; }

    const int mBase = blockIdx.y * 64;
    const int nBase = blockIdx.x * 64;

    load_tile_tf32(X + (size_t)mBase * EE, EE, As, LDK, t);
    load_tile_tf32(W + (size_t)nBase * EE, EE, Bs, LDK, t);
    __syncthreads();

    const int lane = t & 31, warp = t >> 5;
    const int g = lane >> 2, tig = lane & 3;
    const int mb = warp & 3, nh = warp >> 2;

    float acc[4][4];
#pragma unroll
    for (int i = 0; i < 4; i++)
#pragma unroll
        for (int j = 0; j < 4; j++) acc[i][j] = 0.f;

    mma_tile_64x64(As, Bs, acc, mb, nh, g, tig);

    // store fragments to [B,H,S,D] layout
    const int rowLo = mBase + mb * 16 + g;
    const int rowHi = rowLo + 8;
    const int bbL = rowLo >> 10, sL = rowLo & 1023;
    const int bbH = rowHi >> 10, sH = rowHi & 1023;
#pragma unroll
    for (int nt = 0; nt < 4; ++nt) {
        const int col = nBase + nh * 32 + nt * 8 + 2 * tig;
        const int h = col >> 7, d = col & 127;
        *(float2*)(Out + (((size_t)bbL * HHN + h) * SSQ + sL) * DDQ + d) =
            make_float2(acc[nt][0], acc[nt][1]);
        *(float2*)(Out + (((size_t)bbH * HHN + h) * SSQ + sH) * DDQ + d) =
            make_float2(acc[nt][2], acc[nt][3]);
    }
}

// ---------------------------------------------------------------------------
// Kernel 2: flash attention, tf32 mma QK^T and PV (unchanged from R13).
// grid = (16 qTiles, 64 bh), block = 256 (8 warps)
// ---------------------------------------------------------------------------
__global__ __launch_bounds__(256, 2) void attn_kernel(const float* __restrict__ mask)
{
    extern __shared__ float sm[];
    float* Qs   = sm;                          // 64*LDK   (tf32)
    float* KVs  = Qs + 64 * LDK;               // 64*LDV   (K tf32 @LDK, then V tf32 @LDV)
    float* Ss   = KVs + 64 * LDV;              // 64*LDS_
    float* rowM = Ss + 64 * LDS_;              // 64
    float* rowL = rowM + 64;                   // 64
    float* rowA = rowL + 64;                   // 64

    const int t    = threadIdx.x;
    const int lane = t & 31;
    const int warp = t >> 5;
    const int g    = lane >> 2;
    const int tig  = lane & 3;
    const int mb   = warp & 3;
    const int nh   = warp >> 2;

    const int bh = blockIdx.y;
    const int b  = bh >> 3;
    const int qBase = blockIdx.x * 64;

    const float* Qg = g_Q + (size_t)bh * SSQ * DDQ + (size_t)qBase * DDQ;
    const float* Kg = g_K + (size_t)bh * SSQ * DDQ;
    const float* Vg = g_V + (size_t)bh * SSQ * DDQ;

    if (t < 64) { rowM[t] = -INFINITY; rowL[t] = 0.f; }
    load_tile_tf32(Qg, DDQ, Qs, LDK, t);
    __syncthreads();

    const int r = t >> 2, qq = t & 3;
    const float scale = 0.08838834764831845f;  // 1/sqrt(128)
    const float* mrow = mask + (size_t)b * SSQ;

    float o[8][4];
#pragma unroll
    for (int i = 0; i < 8; i++)
#pragma unroll
        for (int j = 0; j < 4; j++) o[i][j] = 0.f;

    const int rowLo = mb * 16 + g;
    const int rowHi = rowLo + 8;

    for (int kb = 0; kb < 16; ++kb) {
        load_tile_tf32(Kg + (size_t)kb * 64 * DDQ, DDQ, KVs, LDK, t);
        __syncthreads();

        // ---- S = Q K^T via mma ----
        float sAcc[4][4];
#pragma unroll
        for (int i = 0; i < 4; i++)
#pragma unroll
            for (int j = 0; j < 4; j++) sAcc[i][j] = 0.f;

        mma_tile_64x64(Qs, KVs, sAcc, mb, nh, g, tig);

#pragma unroll
        for (int nt = 0; nt < 4; ++nt) {
            const int col = nh * 32 + nt * 8 + 2 * tig;
            *(float2*)(Ss + rowLo * LDS_ + col) = make_float2(sAcc[nt][0], sAcc[nt][1]);
            *(float2*)(Ss + rowHi * LDS_ + col) = make_float2(sAcc[nt][2], sAcc[nt][3]);
        }
        __syncthreads();

        // ---- load V block (tf32, stride LDV) into same buffer (K dead) ----
        load_tile_tf32(Vg + (size_t)kb * 64 * DDQ, DDQ, KVs, LDV, t);

        // ---- online softmax ----
        {
            const float* mk = mrow + kb * 64 + qq * 16;
            float vbuf[16];
            float mx = -INFINITY;
#pragma unroll
            for (int c = 0; c < 16; c++) {
                float x = Ss[r * LDS_ + qq * 16 + c] * scale + mk[c];
                vbuf[c] = x;
                mx = fmaxf(mx, x);
            }
            mx = fmaxf(mx, __shfl_xor_sync(0xffffffffu, mx, 1));
            mx = fmaxf(mx, __shfl_xor_sync(0xffffffffu, mx, 2));
            const float mOld = rowM[r];
            const float mNew = fmaxf(mOld, mx);
            float sum = 0.f;
#pragma unroll
            for (int c = 0; c < 16; c++) {
                float p = __expf(vbuf[c] - mNew);
                Ss[r * LDS_ + qq * 16 + c] = __uint_as_float(f2tf(p));
                sum += p;
            }
            sum += __shfl_xor_sync(0xffffffffu, sum, 1);
            sum += __shfl_xor_sync(0xffffffffu, sum, 2);
            if (qq == 0) {
                const float alpha = __expf(mOld - mNew);
                rowL[r] = rowL[r] * alpha + sum;
                rowM[r] = mNew;
                rowA[r] = alpha;
            }
        }
        __syncthreads();

        // ---- rescale O fragments, accumulate P @ V via mma ----
        {
            const float al0 = rowA[rowLo];
            const float al1 = rowA[rowHi];
#pragma unroll
            for (int nt = 0; nt < 8; ++nt) {
                o[nt][0] *= al0;  o[nt][1] *= al0;
                o[nt][2] *= al1;  o[nt][3] *= al1;
            }
#pragma unroll 2
            for (int k8 = 0; k8 < 8; ++k8) {
                const int kk = k8 * 8;
                const float* pb = Ss + rowLo * LDS_ + kk;
                unsigned a0 = __float_as_uint(pb[tig]);
                unsigned a1 = __float_as_uint(pb[8 * LDS_ + tig]);
                unsigned a2 = __float_as_uint(pb[tig + 4]);
                unsigned a3 = __float_as_uint(pb[8 * LDS_ + tig + 4]);
#pragma unroll
                for (int nt = 0; nt < 8; ++nt) {
                    const int n = nh * 64 + nt * 8 + g;
                    unsigned b0 = __float_as_uint(KVs[(kk + tig) * LDV + n]);
                    unsigned b1 = __float_as_uint(KVs[(kk + tig + 4) * LDV + n]);
                    mma_tf32(o[nt], a0, a1, a2, a3, b0, b1);
                }
            }
        }
        __syncthreads();
    }

    // ---- finalize ----
    const int h = bh & 7;
    const float inv0 = 1.f / (rowL[rowLo] + 1e-12f);
    const float inv1 = 1.f / (rowL[rowHi] + 1e-12f);
    float* oLo = g_O + ((size_t)b * SSQ + qBase + rowLo) * HDD + h * DDQ;
    float* oHi = g_O + ((size_t)b * SSQ + qBase + rowHi) * HDD + h * DDQ;
#pragma unroll
    for (int nt = 0; nt < 8; ++nt) {
        const int col = nh * 64 + nt * 8 + 2 * tig;
        *(float2*)(oLo + col) = make_float2(o[nt][0] * inv0, o[nt][1] * inv0);
        *(float2*)(oHi + col) = make_float2(o[nt][2] * inv1, o[nt][3] * inv1);
    }
}

// ---------------------------------------------------------------------------
// Kernel 3: output projection via tf32 mma.  grid=(2,128), block=256
// out[8192,128] = g_O[8192,1024] @ Wc^T + bc
// ---------------------------------------------------------------------------
__global__ __launch_bounds__(256, 2) void oproj_kernel(
    const float* __restrict__ Wc, const float* __restrict__ bc, float* __restrict__ out)
{
    extern __shared__ float sm[];
    float* As = sm;              // g_O tile 64x128 tf32
    float* Bs = sm + 64 * LDK;   // Wc tile 64x128 tf32

    const int t = threadIdx.x;
    const int mBase = blockIdx.y * 64;
    const int nBase = blockIdx.x * 64;

    const int lane = t & 31, warp = t >> 5;
    const int g = lane >> 2, tig = lane & 3;
    const int mb = warp & 3, nh = warp >> 2;

    float acc[4][4];
#pragma unroll
    for (int i = 0; i < 4; i++)
#pragma unroll
        for (int j = 0; j < 4; j++) acc[i][j] = 0.f;

    for (int kc = 0; kc < HDD; kc += 128) {
        __syncthreads();
        load_tile_tf32(g_O + (size_t)mBase * HDD + kc, HDD, As, LDK, t);
        load_tile_tf32(Wc  + (size_t)nBase * HDD + kc, HDD, Bs, LDK, t);
        __syncthreads();
        mma_tile_64x64(As, Bs, acc, mb, nh, g, tig);
    }

    const int rowLo = mBase + mb * 16 + g;
    const int rowHi = rowLo + 8;
#pragma unroll
    for (int nt = 0; nt < 4; ++nt) {
        const int col = nBase + nh * 32 + nt * 8 + 2 * tig;
        const float2 b2 = *(const float2*)(bc + col);
        *(float2*)(out + (size_t)rowLo * EE + col) =
            make_float2(acc[nt][0] + b2.x, acc[nt][1] + b2.y);
        *(float2*)(out + (size_t)rowHi * EE + col) =
            make_float2(acc[nt][2] + b2.x, acc[nt][3] + b2.y);
    }
}

// ---------------------------------------------------------------------------
extern "C" void kernel_launch(void* const* d_in, const int* in_sizes, int n_in,
                              void* d_out, int out_size)
{
    (void)in_sizes; (void)n_in; (void)out_size;
    const float* q    = (const float*)d_in[0];
    const float* k    = (const float*)d_in[1];
    const float* v    = (const float*)d_in[2];
    const float* mask = (const float*)d_in[3];
    const float* Wq   = (const float*)d_in[4];
    const float* Wk   = (const float*)d_in[5];
    const float* Wv   = (const float*)d_in[6];
    const float* Wc   = (const float*)d_in[7];
    const float* bc   = (const float*)d_in[8];
    float* out = (float*)d_out;

    const int gemmSmem = 2 * 64 * LDK * 4;                                  // 67584 B
    const int attnSmem = (64 * LDK + 64 * LDV + 64 * LDS_ + 3 * 64) * 4;    // 86784 B

    cudaFuncSetAttribute(proj_kernel,  cudaFuncAttributeMaxDynamicSharedMemorySize, gemmSmem);
    cudaFuncSetAttribute(attn_kernel,  cudaFuncAttributeMaxDynamicSharedMemorySize, attnSmem);
    cudaFuncSetAttribute(oproj_kernel, cudaFuncAttributeMaxDynamicSharedMemorySize, gemmSmem);

    proj_kernel <<<dim3(16, 128, 3), 256, gemmSmem>>>(q, k, v, Wq, Wk, Wv);
    attn_kernel <<<dim3(16, 64),     256, attnSmem>>>(mask);
    oproj_kernel<<<dim3(2, 128),     256, gemmSmem>>>(Wc, bc, out);
}